// round 1
// baseline (speedup 1.0000x reference)
#include <cuda_runtime.h>
#include <math.h>

// Problem constants (match reference)
#define Hd 512
#define Wd 512
#define NSEG 64            // (193-1)/3
#define NPTS 2048          // NSEG * 32 samples
#define NTHREADS 256
#define RADIUS 20.0f       // sigmoid support cutoff: sigma(-20) ~ 2e-9

__device__ __forceinline__ float fast_sigmoid(float z) {
    // 1/(1+e^-z); __expf error ~2 ulp, fine vs 1e-3 gate
    return 1.0f / (1.0f + __expf(-z));
}

__global__ __launch_bounds__(NTHREADS)
void bezier_row_kernel(const float* __restrict__ cp,
                       const float* __restrict__ color,
                       float* __restrict__ out) {
    __shared__ float2 s_path[NPTS];        // 16 KB
    __shared__ float  s_acc[Wd];           // transition accumulation
    __shared__ float  s_carry[Wd + 1];     // full-weight step buckets

    const int tid = threadIdx.x;
    const int y   = blockIdx.x;
    const float gy = (float)y;

    // --- Phase 1: compute 2048 Bezier samples into shared (8 per thread) ---
    const float2* c2 = (const float2*)cp;  // 193 control points, 8B aligned
    #pragma unroll
    for (int i = 0; i < NPTS / NTHREADS; ++i) {
        int idx = tid + i * NTHREADS;
        int seg = idx >> 5;        // /32
        int k   = idx & 31;
        float t  = (float)k * (1.0f / 31.0f);
        float mt = 1.0f - t;
        float2 p0 = c2[3 * seg + 0];
        float2 p1 = c2[3 * seg + 1];
        float2 p2 = c2[3 * seg + 2];
        float2 p3 = c2[3 * seg + 3];
        float w0 = mt * mt * mt;
        float w1 = 3.0f * mt * mt * t;
        float w2 = 3.0f * mt * t * t;
        float w3 = t * t * t;
        s_path[idx] = make_float2(
            w0 * p0.x + w1 * p1.x + w2 * p2.x + w3 * p3.x,
            w0 * p0.y + w1 * p1.y + w2 * p2.y + w3 * p3.y);
    }

    // --- zero row accumulators ---
    for (int i = tid; i < Wd; i += NTHREADS) s_acc[i] = 0.0f;
    for (int i = tid; i <= Wd; i += NTHREADS) s_carry[i] = 0.0f;
    __syncthreads();

    // --- Phase 2: scan all edges for this row ---
    for (int e = tid; e < NPTS; e += NTHREADS) {
        float2 a = s_path[e];
        float2 b = s_path[(e + 1) & (NPTS - 1)];
        float dy = b.y - a.y;
        if (fabsf(dy) < 1e-6f) continue;             // reference mask == 0
        float t = (gy - a.y) / (dy + 1e-8f);
        // valid_t = sig(20t)*sig(20(1-t)) <= ~1e-13 outside this band
        if (t < -1.5f || t > 2.5f) continue;
        float w = fast_sigmoid(20.0f * t) * fast_sigmoid(20.0f * (1.0f - t));
        w = (dy > 0.0f) ? w : -w;                    // * sign(dy)
        float xc = fmaf(t, b.x - a.x, a.x);          // x crossing

        int lo = (int)ceilf(xc - RADIUS);
        int hi = (int)floorf(xc + RADIUS);
        // full weight for all x < lo  ->  bucket at clamp(lo,0,Wd)
        int ci = min(max(lo, 0), Wd);
        atomicAdd(&s_carry[ci], w);
        // transition window
        int x0 = max(lo, 0);
        int x1 = min(hi, Wd - 1);
        for (int x = x0; x <= x1; ++x) {
            float s = fast_sigmoid(xc - (float)x);
            atomicAdd(&s_acc[x], w * s);
        }
    }
    __syncthreads();

    // --- Phase 3: suffix-sum the carry buckets into acc ---
    // wind(x) = acc(x) + sum_{j > x} carry[j]
    if (tid == 0) {
        float r = 0.0f;
        #pragma unroll 4
        for (int x = Wd - 1; x >= 0; --x) {
            r += s_carry[x + 1];
            s_acc[x] += r;
        }
    }
    __syncthreads();

    // --- Phase 4: alpha + RGBA output ---
    float cr = color[0], cg = color[1], cb = color[2];
    float4* out4 = (float4*)out;
    for (int x = tid; x < Wd; x += NTHREADS) {
        float wind = s_acc[x];
        float alpha = fast_sigmoid(4.0f * wind);
        out4[y * Wd + x] = make_float4(cr, cg, cb, alpha);
    }
}

extern "C" void kernel_launch(void* const* d_in, const int* in_sizes, int n_in,
                              void* d_out, int out_size) {
    (void)in_sizes; (void)n_in; (void)out_size;
    const float* cp    = (const float*)d_in[0];   // (193,2) float32
    const float* color = (const float*)d_in[1];   // (3,)   float32
    float* out = (float*)d_out;                   // (512,512,4) float32
    bezier_row_kernel<<<Hd, NTHREADS>>>(cp, color, out);
}

// round 2
// speedup vs baseline: 2.7144x; 2.7144x over previous
#include <cuda_runtime.h>
#include <math.h>

#define Hd 512
#define Wd 512
#define NPTS 2048           // 64 segments * 32 samples
#define NT 512              // one thread per output pixel / per edge-lane
#define RADIUS 16.0f        // sigma(-16) = 1.1e-7 truncation

// Precomputed edge table: (x0, y0, dx, inv_dy). Masked edges: y0 = NaN.
__device__ float4 g_edge[NPTS];

__device__ __forceinline__ float fsig(float z) {
    // fast sigmoid: MUFU.EX2 + MUFU.RCP path
    return __fdividef(1.0f, 1.0f + __expf(-z));
}

// ---------------- Kernel 1: sample Beziers + build edge table (runs once, tiny) ----
__global__ __launch_bounds__(NT)
void build_edges(const float* __restrict__ cp) {
    __shared__ float2 pts[NPTS];
    const int tid = threadIdx.x;
    const float2* c2 = (const float2*)cp;    // 193 control points
    #pragma unroll
    for (int i = 0; i < NPTS / NT; ++i) {
        int idx = tid + i * NT;
        int seg = idx >> 5;
        int k   = idx & 31;
        float t  = (float)k * (1.0f / 31.0f);
        float mt = 1.0f - t;
        float2 p0 = c2[3 * seg + 0];
        float2 p1 = c2[3 * seg + 1];
        float2 p2 = c2[3 * seg + 2];
        float2 p3 = c2[3 * seg + 3];
        float w0 = mt * mt * mt;
        float w1 = 3.0f * mt * mt * t;
        float w2 = 3.0f * mt * t * t;
        float w3 = t * t * t;
        pts[idx] = make_float2(
            w0 * p0.x + w1 * p1.x + w2 * p2.x + w3 * p3.x,
            w0 * p0.y + w1 * p1.y + w2 * p2.y + w3 * p3.y);
    }
    __syncthreads();
    #pragma unroll
    for (int i = 0; i < NPTS / NT; ++i) {
        int idx = tid + i * NT;
        float2 a = pts[idx];
        float2 b = pts[(idx + 1) & (NPTS - 1)];
        float dy = b.y - a.y;
        float y0 = a.y;
        float invdy = 1.0f / (dy + 1e-8f);   // host-precision div, once
        if (fabsf(dy) < 1e-6f) {             // reference mask==0 -> kill edge
            y0 = __int_as_float(0x7fffffff); // NaN -> t=NaN -> rejected below
            invdy = 0.0f;
        }
        g_edge[idx] = make_float4(a.x, y0, b.x - a.x, invdy);
    }
}

// ---------------- Kernel 2: one block per row --------------------------------------
__global__ __launch_bounds__(NT)
void render_rows(const float* __restrict__ color, float* __restrict__ out) {
    __shared__ float s_acc[Wd];        // transition accumulation
    __shared__ float s_carry[Wd + 1];  // full-weight step buckets
    __shared__ float s_wsum[16];       // scan cross-warp temps

    const int tid = threadIdx.x;
    const int y   = blockIdx.x;
    const float gy = (float)y;

    s_acc[tid] = 0.0f;
    s_carry[tid] = 0.0f;
    if (tid == 0) s_carry[Wd] = 0.0f;
    __syncthreads();

    // --- edge scan: 4 edges per thread ---
    #pragma unroll
    for (int i = 0; i < NPTS / NT; ++i) {
        int e = tid + i * NT;
        float4 E = g_edge[e];                  // (x0, y0, dx, inv_dy)
        float t = (gy - E.y) * E.w;
        // NaN-rejecting band test; sigma(20*1)=2e-9 beyond [-1,2]
        if (!(t >= -1.0f && t <= 2.0f)) continue;
        float w = fsig(20.0f * t) * fsig(20.0f - 20.0f * t);
        w = copysignf(w, E.w);                 // sign(dy)
        float xc = fmaf(t, E.z, E.x);

        int lo = (int)ceilf(xc - RADIUS);
        int hi = (int)floorf(xc + RADIUS);
        int ci = min(max(lo, 0), Wd);
        atomicAdd(&s_carry[ci], w);            // full weight for x < lo

        int x0 = max(lo, 0);
        int x1 = min(hi, Wd - 1);
        if (x0 <= x1) {
            // sigma(xc - x) = 1/(1+u), u = e^(x-xc); one EX2, then u *= e
            float u = __expf((float)x0 - xc);
            const float EC = 2.7182818284590452f;
            for (int x = x0; x <= x1; ++x) {
                atomicAdd(&s_acc[x], w * __fdividef(1.0f, 1.0f + u));
                u *= EC;
            }
        }
    }
    __syncthreads();

    // --- parallel suffix scan of carry: S[x] = sum_{j>x} carry[j] ---
    // thread tid scans v = carry[512 - tid]; inclusive prefix P[tid] = sum_{j>=512-tid} carry[j]
    float v = s_carry[Wd - tid];
    __syncthreads();                            // all reads done before reuse
    const int lane = tid & 31, wid = tid >> 5;
    float val = v;
    #pragma unroll
    for (int o = 1; o < 32; o <<= 1) {
        float n = __shfl_up_sync(0xffffffffu, val, o);
        if (lane >= o) val += n;
    }
    if (lane == 31) s_wsum[wid] = val;
    __syncthreads();
    if (wid == 0) {
        float s = (lane < 16) ? s_wsum[lane] : 0.0f;
        #pragma unroll
        for (int o = 1; o < 16; o <<= 1) {
            float n = __shfl_up_sync(0xffffffffu, s, o);
            if (lane >= o) s += n;
        }
        if (lane < 16) s_wsum[lane] = s;        // inclusive warp-sum scan
    }
    __syncthreads();
    if (wid > 0) val += s_wsum[wid - 1];
    s_carry[tid] = val;                         // P[tid]
    __syncthreads();

    // --- output: wind[x] = acc[x] + P[511-x]; alpha = sigmoid(4*wind) ---
    float wind  = s_acc[tid] + s_carry[(Wd - 1) - tid];
    float alpha = fsig(4.0f * wind);
    ((float4*)out)[y * Wd + tid] =
        make_float4(color[0], color[1], color[2], alpha);
}

extern "C" void kernel_launch(void* const* d_in, const int* in_sizes, int n_in,
                              void* d_out, int out_size) {
    (void)in_sizes; (void)n_in; (void)out_size;
    const float* cp    = (const float*)d_in[0];   // (193,2) float32
    const float* color = (const float*)d_in[1];   // (3,)    float32
    float* out = (float*)d_out;                   // (512,512,4) float32
    build_edges<<<1, NT>>>(cp);
    render_rows<<<Hd, NT>>>(color, out);
}

// round 3
// speedup vs baseline: 4.7050x; 1.7333x over previous
#include <cuda_runtime.h>
#include <math.h>

#define Hd 512
#define Wd 512
#define NPTS 2048           // 64 segments * 32 samples
#define NT 512
#define RADIUS 16.0f        // sigma(-16) = 1.1e-7 truncation
#define MAXACT (NPTS + 8)

// Precomputed edge table: (x0, y0, dx, inv_dy). Masked edges: y0 = NaN.
__device__ float4 g_edge[NPTS];

__device__ __forceinline__ float fsig(float z) {
    return __fdividef(1.0f, 1.0f + __expf(-z));
}

// ---- Kernel 1: sample Beziers + build edge table (tiny, runs once) ----
__global__ __launch_bounds__(NT)
void build_edges(const float* __restrict__ cp) {
    __shared__ float2 pts[NPTS];
    const int tid = threadIdx.x;
    const float2* c2 = (const float2*)cp;        // 193 control points
    #pragma unroll
    for (int i = 0; i < NPTS / NT; ++i) {
        int idx = tid + i * NT;
        int seg = idx >> 5;
        int k   = idx & 31;
        float t  = (float)k * (1.0f / 31.0f);
        float mt = 1.0f - t;
        float2 p0 = c2[3 * seg + 0];
        float2 p1 = c2[3 * seg + 1];
        float2 p2 = c2[3 * seg + 2];
        float2 p3 = c2[3 * seg + 3];
        float w0 = mt * mt * mt;
        float w1 = 3.0f * mt * mt * t;
        float w2 = 3.0f * mt * t * t;
        float w3 = t * t * t;
        pts[idx] = make_float2(
            w0 * p0.x + w1 * p1.x + w2 * p2.x + w3 * p3.x,
            w0 * p0.y + w1 * p1.y + w2 * p2.y + w3 * p3.y);
    }
    __syncthreads();
    #pragma unroll
    for (int i = 0; i < NPTS / NT; ++i) {
        int idx = tid + i * NT;
        float2 a = pts[idx];
        float2 b = pts[(idx + 1) & (NPTS - 1)];
        float dy = b.y - a.y;
        float y0 = a.y;
        float invdy = 1.0f / (dy + 1e-8f);
        if (fabsf(dy) < 1e-6f) {                 // reference mask==0 -> kill edge
            y0 = __int_as_float(0x7fffffff);     // NaN -> band test rejects
            invdy = 0.0f;
        }
        g_edge[idx] = make_float4(a.x, y0, b.x - a.x, invdy);
    }
}

// ---- Kernel 2: one block per row; pixel-per-thread register accumulation ----
__global__ __launch_bounds__(NT)
void render_rows(const float* __restrict__ color, float* __restrict__ out) {
    __shared__ float2 s_act[MAXACT];   // compacted active edges: (xc, w)
    __shared__ float  s_carry[Wd + 1]; // full-weight step buckets
    __shared__ float  s_wsum[16];
    __shared__ int    s_n;

    const int tid = threadIdx.x;
    const int y   = blockIdx.x;
    const float gy = (float)y;

    s_carry[tid] = 0.0f;
    if (tid == 0) { s_carry[Wd] = 0.0f; s_n = 0; }
    __syncthreads();

    // --- Phase A: band test + compaction (4 edges per thread) ---
    #pragma unroll
    for (int i = 0; i < NPTS / NT; ++i) {
        int e = tid + i * NT;
        float4 E = g_edge[e];                  // (x0, y0, dx, inv_dy)
        float t = (gy - E.y) * E.w;
        if (!(t >= -1.0f && t <= 2.0f)) continue;   // NaN-rejecting
        float w = fsig(20.0f * t) * fsig(20.0f - 20.0f * t);
        w = copysignf(w, E.w);                 // sign(dy)
        float xc = fmaf(t, E.z, E.x);
        // full weight for x < ceil(xc - R) -> carry bucket
        int ci = min(max((int)ceilf(xc - RADIUS), 0), Wd);
        atomicAdd(&s_carry[ci], w);
        int p = atomicAdd(&s_n, 1);
        s_act[p] = make_float2(xc, w);
    }
    __syncthreads();

    // pad list to multiple of 8 with far-away sentinels
    int n = s_n;
    int npad = (n + 7) & ~7;
    if (tid < npad - n) s_act[n + tid] = make_float2(1.0e9f, 0.0f);
    __syncthreads();

    // --- Phase B: each thread owns pixel x = tid, accumulates in register ---
    float wind = 0.0f;
    const float fx = (float)tid;
    #pragma unroll 8
    for (int i = 0; i < npad; ++i) {
        float2 E = s_act[i];                   // broadcast LDS
        float z = E.x - fx;
        if (fabsf(z) <= RADIUS) {
            wind += E.y * fsig(z);             // x>=ci <=> z<=R (exact match w/ carry)
        }
    }
    __syncthreads();

    // --- parallel suffix scan of carry: P[tid] = sum_{j >= 512-tid} carry[j] ---
    float v = s_carry[Wd - tid];
    __syncthreads();
    const int lane = tid & 31, wid = tid >> 5;
    float val = v;
    #pragma unroll
    for (int o = 1; o < 32; o <<= 1) {
        float nb = __shfl_up_sync(0xffffffffu, val, o);
        if (lane >= o) val += nb;
    }
    if (lane == 31) s_wsum[wid] = val;
    __syncthreads();
    if (wid == 0) {
        float s = (lane < 16) ? s_wsum[lane] : 0.0f;
        #pragma unroll
        for (int o = 1; o < 16; o <<= 1) {
            float nb = __shfl_up_sync(0xffffffffu, s, o);
            if (lane >= o) s += nb;
        }
        if (lane < 16) s_wsum[lane] = s;
    }
    __syncthreads();
    if (wid > 0) val += s_wsum[wid - 1];
    s_carry[tid] = val;                        // P[tid]
    __syncthreads();

    // --- output: wind += sum_{j > x} carry[j] = P[511 - x] ---
    wind += s_carry[(Wd - 1) - tid];
    float alpha = fsig(4.0f * wind);
    ((float4*)out)[y * Wd + tid] =
        make_float4(color[0], color[1], color[2], alpha);
}

extern "C" void kernel_launch(void* const* d_in, const int* in_sizes, int n_in,
                              void* d_out, int out_size) {
    (void)in_sizes; (void)n_in; (void)out_size;
    const float* cp    = (const float*)d_in[0];   // (193,2) float32
    const float* color = (const float*)d_in[1];   // (3,)    float32
    float* out = (float*)d_out;                   // (512,512,4) float32
    build_edges<<<1, NT>>>(cp);
    render_rows<<<Hd, NT>>>(color, out);
}

// round 4
// speedup vs baseline: 6.0064x; 1.2766x over previous
#include <cuda_runtime.h>
#include <math.h>

#define Hd 512
#define Wd 512
#define NPTS 2048           // 64 segments * 32 samples
#define NT 512
#define RADIUS 16.0f        // sigma(-16) = 1.1e-7 truncation
#define NBIN 16             // 32-pixel column bins
#define CAP 192             // per-bin active-edge capacity

__device__ __forceinline__ float fsig(float z) {
    return __fdividef(1.0f, 1.0f + __expf(-z));
}

// One block per row; fused: Bezier sampling + edge binning + pixel accumulation.
__global__ __launch_bounds__(NT)
void render_rows(const float* __restrict__ cp,
                 const float* __restrict__ color,
                 float* __restrict__ out) {
    __shared__ float2 s_pts[NPTS];         // 16 KB  sampled path
    __shared__ float2 s_bin[NBIN][CAP];    // 24 KB  binned active edges (xc, w)
    __shared__ int    s_cnt[NBIN];
    __shared__ float  s_carry[Wd + 1];     // full-weight step buckets
    __shared__ float  s_wsum[16];

    const int tid = threadIdx.x;
    const int y   = blockIdx.x;
    const float gy = (float)y;

    // --- Phase 0: sample Beziers into shared (4 points per thread) ---
    const float2* c2 = (const float2*)cp;           // 193 control points
    #pragma unroll
    for (int i = 0; i < NPTS / NT; ++i) {
        int idx = tid + i * NT;
        int seg = idx >> 5;
        int k   = idx & 31;
        float t  = (float)k * (1.0f / 31.0f);
        float mt = 1.0f - t;
        float2 p0 = c2[3 * seg + 0];
        float2 p1 = c2[3 * seg + 1];
        float2 p2 = c2[3 * seg + 2];
        float2 p3 = c2[3 * seg + 3];
        float w0 = mt * mt * mt;
        float w1 = 3.0f * mt * mt * t;
        float w2 = 3.0f * mt * t * t;
        float w3 = t * t * t;
        s_pts[idx] = make_float2(
            w0 * p0.x + w1 * p1.x + w2 * p2.x + w3 * p3.x,
            w0 * p0.y + w1 * p1.y + w2 * p2.y + w3 * p3.y);
    }
    s_carry[tid] = 0.0f;
    if (tid == 0) s_carry[Wd] = 0.0f;
    if (tid < NBIN) s_cnt[tid] = 0;
    __syncthreads();

    // --- Phase A: band test + bin insertion (4 edges per thread) ---
    #pragma unroll
    for (int i = 0; i < NPTS / NT; ++i) {
        int e = tid + i * NT;
        float2 a = s_pts[e];
        float2 b = s_pts[(e + 1) & (NPTS - 1)];
        float dy = b.y - a.y;
        if (fabsf(dy) < 1e-6f) continue;            // reference mask==0
        float t = (gy - a.y) * __fdividef(1.0f, dy + 1e-8f);
        if (!(t >= -1.0f && t <= 2.0f)) continue;   // sig(20)=2e-9 beyond band
        float w = fsig(20.0f * t) * fsig(20.0f - 20.0f * t);
        w = (dy > 0.0f) ? w : -w;                   // sign(dy)
        float xc = fmaf(t, b.x - a.x, a.x);

        // full weight for x < ceil(xc - R) -> carry bucket (suffix-scanned later)
        int ci = min(max((int)ceilf(xc - RADIUS), 0), Wd);
        atomicAdd(&s_carry[ci], w);

        // transition window -> spatial bin by xc
        int bi = min(max((int)floorf(xc * (1.0f / 32.0f)), 0), NBIN - 1);
        int p  = atomicAdd(&s_cnt[bi], 1);
        if (p < CAP) s_bin[bi][p] = make_float2(xc, w);
    }
    __syncthreads();

    // --- Phase B: thread owns pixel x = tid; warp scans its 3 nearby bins ---
    float wind = 0.0f;
    {
        const float fx = (float)tid;
        const int wp = tid >> 5;
        const int b0 = max(wp - 1, 0);
        const int b1 = min(wp + 1, NBIN - 1);
        for (int b = b0; b <= b1; ++b) {
            int n = min(s_cnt[b], CAP);
            for (int i = 0; i < n; ++i) {
                float2 E = s_bin[b][i];             // broadcast LDS
                float z = E.x - fx;
                if (fabsf(z) <= RADIUS)
                    wind += E.y * fsig(z);          // x>=ci <=> z<=R
            }
        }
    }
    __syncthreads();

    // --- suffix scan of carry: P[tid] = sum_{j >= 512-tid} carry[j] ---
    float v = s_carry[Wd - tid];
    __syncthreads();
    const int lane = tid & 31, wid = tid >> 5;
    float val = v;
    #pragma unroll
    for (int o = 1; o < 32; o <<= 1) {
        float nb = __shfl_up_sync(0xffffffffu, val, o);
        if (lane >= o) val += nb;
    }
    if (lane == 31) s_wsum[wid] = val;
    __syncthreads();
    if (wid == 0) {
        float s = (lane < 16) ? s_wsum[lane] : 0.0f;
        #pragma unroll
        for (int o = 1; o < 16; o <<= 1) {
            float nb = __shfl_up_sync(0xffffffffu, s, o);
            if (lane >= o) s += nb;
        }
        if (lane < 16) s_wsum[lane] = s;
    }
    __syncthreads();
    if (wid > 0) val += s_wsum[wid - 1];
    s_carry[tid] = val;                             // P[tid]
    __syncthreads();

    // --- output: wind += sum_{j > x} carry[j] = P[511 - x] ---
    wind += s_carry[(Wd - 1) - tid];
    float alpha = fsig(4.0f * wind);
    ((float4*)out)[y * Wd + tid] =
        make_float4(color[0], color[1], color[2], alpha);
}

extern "C" void kernel_launch(void* const* d_in, const int* in_sizes, int n_in,
                              void* d_out, int out_size) {
    (void)in_sizes; (void)n_in; (void)out_size;
    const float* cp    = (const float*)d_in[0];   // (193,2) float32
    const float* color = (const float*)d_in[1];   // (3,)    float32
    float* out = (float*)d_out;                   // (512,512,4) float32
    render_rows<<<Hd, NT>>>(cp, color, out);
}